// round 12
// baseline (speedup 1.0000x reference)
#include <cuda_runtime.h>
#include <cuda_bf16.h>
#include <math.h>

// Problem constants (fixed shapes for this problem instance)
#define GC_IN   512
#define GC_OUT  256
#define GC_NMAX 100000
#define GC_EMAX 3200000

// Scratch buffers (device globals — no allocation allowed)
__device__ float g_support[(size_t)GC_NMAX * GC_OUT];     // tanh(x@W)
__device__ int   g_counts [GC_NMAX];
__device__ int   g_offsets[GC_NMAX + 1];
__device__ int   g_cursor [GC_NMAX];
__device__ int   g_perm   [GC_EMAX];
__device__ int   g_partials[128];

// ---------------------------------------------------------------------------
// Kernel 1: SGEMM (M=N_nodes, K=512, N=256) with optional tanh epilogue.
// 128x128x16 tile, 8x8 register blocking, 256 threads. (unchanged from R1)
// ---------------------------------------------------------------------------
#define BM 128
#define BN 128
#define BK 16
#define TM 8
#define TN 8

__global__ __launch_bounds__(256, 2)
void gemm_tanh_kernel(const float* __restrict__ A,   // [M, 512]
                      const float* __restrict__ B,   // [512, 256]
                      const int*   __restrict__ active,
                      int M)
{
    const int K = GC_IN;
    const int N = GC_OUT;

    __shared__ float As[BK][BM];
    __shared__ float Bs[BK][BN];

    const int bcol = blockIdx.x;
    const int brow = blockIdx.y;
    const int tid  = threadIdx.x;

    const int tcol = tid % (BN / TN);
    const int trow = tid / (BN / TN);

    const int aInnerRow = tid / (BK / 4);
    const int aInnerCol = (tid % (BK / 4)) * 4;

    const int bInnerRow = tid / (BN / 4);
    const int bInnerCol = (tid % (BN / 4)) * 4;

    float acc[TM][TN];
    #pragma unroll
    for (int m = 0; m < TM; m++)
        #pragma unroll
        for (int n = 0; n < TN; n++)
            acc[m][n] = 0.0f;

    const int rowBase = brow * BM;

    for (int kb = 0; kb < K; kb += BK) {
        #pragma unroll
        for (int i = 0; i < BM; i += 64) {
            int r = rowBase + aInnerRow + i;
            float4 v;
            if (r < M) {
                v = *(const float4*)(A + (size_t)r * K + kb + aInnerCol);
            } else {
                v = make_float4(0.f, 0.f, 0.f, 0.f);
            }
            As[aInnerCol + 0][aInnerRow + i] = v.x;
            As[aInnerCol + 1][aInnerRow + i] = v.y;
            As[aInnerCol + 2][aInnerRow + i] = v.z;
            As[aInnerCol + 3][aInnerRow + i] = v.w;
        }
        #pragma unroll
        for (int i = 0; i < BK; i += 8) {
            int r = kb + bInnerRow + i;
            float4 v = *(const float4*)(B + (size_t)r * N + bcol * BN + bInnerCol);
            *(float4*)(&Bs[bInnerRow + i][bInnerCol]) = v;
        }
        __syncthreads();

        #pragma unroll
        for (int k = 0; k < BK; k++) {
            float regM[TM], regN[TN];
            #pragma unroll
            for (int m = 0; m < TM; m++) regM[m] = As[k][trow * TM + m];
            #pragma unroll
            for (int n = 0; n < TN; n++) regN[n] = Bs[k][tcol * TN + n];
            #pragma unroll
            for (int m = 0; m < TM; m++)
                #pragma unroll
                for (int n = 0; n < TN; n++)
                    acc[m][n] = fmaf(regM[m], regN[n], acc[m][n]);
        }
        __syncthreads();
    }

    const int act = active[0];

    #pragma unroll
    for (int m = 0; m < TM; m++) {
        int r = rowBase + trow * TM + m;
        if (r >= M) continue;
        #pragma unroll
        for (int n = 0; n < TN; n += 4) {
            int c = bcol * BN + tcol * TN + n;
            float4 v;
            v.x = acc[m][n + 0];
            v.y = acc[m][n + 1];
            v.z = acc[m][n + 2];
            v.w = acc[m][n + 3];
            if (act) {
                v.x = tanhf(v.x); v.y = tanhf(v.y);
                v.z = tanhf(v.z); v.w = tanhf(v.w);
            }
            *(float4*)(&g_support[(size_t)r * GC_OUT + c]) = v;
        }
    }
}

// ---------------------------------------------------------------------------
// CSR binning: zero counts -> histogram -> 3-kernel exclusive scan -> bin
// ---------------------------------------------------------------------------
__global__ void zero_counts_kernel(int N)
{
    int i = blockIdx.x * blockDim.x + threadIdx.x;
    if (i < N) g_counts[i] = 0;
}

__global__ void hist_kernel(const int* __restrict__ rows, int E)
{
    int i = blockIdx.x * blockDim.x + threadIdx.x;
    if (i < E) atomicAdd(&g_counts[rows[i]], 1);
}

#define SCAN_B 1024

// chunk-local exclusive scan, chunk totals to g_partials
__global__ __launch_bounds__(SCAN_B)
void scan1_kernel(int N)
{
    __shared__ int s[SCAN_B];
    int chunk = blockIdx.x;
    int i = chunk * SCAN_B + threadIdx.x;
    int v = (i < N) ? g_counts[i] : 0;
    s[threadIdx.x] = v;
    __syncthreads();
    for (int d = 1; d < SCAN_B; d <<= 1) {
        int t = (threadIdx.x >= d) ? s[threadIdx.x - d] : 0;
        __syncthreads();
        s[threadIdx.x] += t;
        __syncthreads();
    }
    if (i < N) g_offsets[i] = s[threadIdx.x] - v;     // exclusive, chunk-local
    if (threadIdx.x == SCAN_B - 1) g_partials[chunk] = s[SCAN_B - 1];
}

// exclusive scan of chunk totals (nchunks <= 128)
__global__ __launch_bounds__(128)
void scan2_kernel(int nchunks)
{
    __shared__ int s[128];
    int v = (threadIdx.x < nchunks) ? g_partials[threadIdx.x] : 0;
    s[threadIdx.x] = v;
    __syncthreads();
    for (int d = 1; d < 128; d <<= 1) {
        int t = (threadIdx.x >= d) ? s[threadIdx.x - d] : 0;
        __syncthreads();
        s[threadIdx.x] += t;
        __syncthreads();
    }
    if (threadIdx.x < nchunks) g_partials[threadIdx.x] = s[threadIdx.x] - v;
}

// add chunk base; init cursor; set offsets[N] = E
__global__ __launch_bounds__(SCAN_B)
void scan3_kernel(int N, int E)
{
    int i = blockIdx.x * SCAN_B + threadIdx.x;
    if (i < N) {
        int o = g_offsets[i] + g_partials[blockIdx.x];
        g_offsets[i] = o;
        g_cursor[i]  = o;
    }
    if (i == 0) g_offsets[N] = E;
}

__global__ void bin_kernel(const int* __restrict__ rows, int E)
{
    int i = blockIdx.x * blockDim.x + threadIdx.x;
    if (i < E) {
        int pos = atomicAdd(&g_cursor[rows[i]], 1);
        g_perm[pos] = i;
    }
}

// ---------------------------------------------------------------------------
// Kernel 3: CSR SpMM, one warp per output row, no atomics.
// acc[8] fp32 per lane (lane covers float4 #lane and #lane+32 of the row).
// ---------------------------------------------------------------------------
__global__ __launch_bounds__(256)
void spmm_csr_kernel(const int*   __restrict__ cols,
                     const float* __restrict__ vals,
                     float*       __restrict__ out,
                     int N)
{
    int warp = (blockIdx.x * blockDim.x + threadIdx.x) >> 5;
    int lane = threadIdx.x & 31;
    if (warp >= N) return;

    int beg = g_offsets[warp];
    int end = g_offsets[warp + 1];

    float4 a0 = make_float4(0.f, 0.f, 0.f, 0.f);
    float4 a1 = make_float4(0.f, 0.f, 0.f, 0.f);

    const float4* base = (const float4*)g_support;

    int idx = beg;
    for (; idx + 1 < end; idx += 2) {
        int e0 = g_perm[idx];
        int e1 = g_perm[idx + 1];
        int   c0 = __ldg(cols + e0);
        int   c1 = __ldg(cols + e1);
        float v0 = __ldg(vals + e0);
        float v1 = __ldg(vals + e1);
        const float4* s0 = base + (size_t)c0 * (GC_OUT / 4);
        const float4* s1 = base + (size_t)c1 * (GC_OUT / 4);
        float4 p00 = __ldg(s0 + lane);
        float4 p01 = __ldg(s0 + 32 + lane);
        float4 p10 = __ldg(s1 + lane);
        float4 p11 = __ldg(s1 + 32 + lane);
        a0.x = fmaf(v0, p00.x, a0.x); a0.y = fmaf(v0, p00.y, a0.y);
        a0.z = fmaf(v0, p00.z, a0.z); a0.w = fmaf(v0, p00.w, a0.w);
        a1.x = fmaf(v0, p01.x, a1.x); a1.y = fmaf(v0, p01.y, a1.y);
        a1.z = fmaf(v0, p01.z, a1.z); a1.w = fmaf(v0, p01.w, a1.w);
        a0.x = fmaf(v1, p10.x, a0.x); a0.y = fmaf(v1, p10.y, a0.y);
        a0.z = fmaf(v1, p10.z, a0.z); a0.w = fmaf(v1, p10.w, a0.w);
        a1.x = fmaf(v1, p11.x, a1.x); a1.y = fmaf(v1, p11.y, a1.y);
        a1.z = fmaf(v1, p11.z, a1.z); a1.w = fmaf(v1, p11.w, a1.w);
    }
    if (idx < end) {
        int e0 = g_perm[idx];
        int   c0 = __ldg(cols + e0);
        float v0 = __ldg(vals + e0);
        const float4* s0 = base + (size_t)c0 * (GC_OUT / 4);
        float4 p00 = __ldg(s0 + lane);
        float4 p01 = __ldg(s0 + 32 + lane);
        a0.x = fmaf(v0, p00.x, a0.x); a0.y = fmaf(v0, p00.y, a0.y);
        a0.z = fmaf(v0, p00.z, a0.z); a0.w = fmaf(v0, p00.w, a0.w);
        a1.x = fmaf(v0, p01.x, a1.x); a1.y = fmaf(v0, p01.y, a1.y);
        a1.z = fmaf(v0, p01.z, a1.z); a1.w = fmaf(v0, p01.w, a1.w);
    }

    float4* o = (float4*)(out + (size_t)warp * GC_OUT);
    o[lane]      = a0;
    o[lane + 32] = a1;
}

// ---------------------------------------------------------------------------
// Launch
// ---------------------------------------------------------------------------
extern "C" void kernel_launch(void* const* d_in, const int* in_sizes, int n_in,
                              void* d_out, int out_size)
{
    const float* x      = (const float*)d_in[0];
    const float* weight = (const float*)d_in[1];
    const int*   erows  = (const int*)d_in[2];
    const int*   ecols  = (const int*)d_in[3];
    const float* evals  = (const float*)d_in[4];
    const int*   active = (const int*)d_in[5];
    float* out = (float*)d_out;

    int N = in_sizes[0] / GC_IN;    // 100000
    int E = in_sizes[2];            // 3200000

    // 1) support = tanh(x @ W)
    dim3 ggrid(GC_OUT / BN, (N + BM - 1) / BM);
    gemm_tanh_kernel<<<ggrid, 256>>>(x, weight, active, N);

    // 2) CSR binning (runs concurrently-independent of GEMM except spmm)
    int nchunks = (N + SCAN_B - 1) / SCAN_B;          // 98
    zero_counts_kernel<<<(N + 255) / 256, 256>>>(N);
    hist_kernel<<<(E + 255) / 256, 256>>>(erows, E);
    scan1_kernel<<<nchunks, SCAN_B>>>(N);
    scan2_kernel<<<1, 128>>>(nchunks);
    scan3_kernel<<<nchunks, SCAN_B>>>(N, E);
    bin_kernel<<<(E + 255) / 256, 256>>>(erows, E);

    // 3) CSR SpMM: one warp per row, writes out exactly once (no zeroing, no atomics)
    long long threads = (long long)N * 32;
    int blocks = (int)((threads + 255) / 256);
    spmm_csr_kernel<<<blocks, 256>>>(ecols, evals, out, N);
}

// round 13
// speedup vs baseline: 1.0001x; 1.0001x over previous
#include <cuda_runtime.h>
#include <cuda_bf16.h>
#include <math.h>

// Problem constants (fixed shapes for this problem instance)
#define GC_IN   512
#define GC_OUT  256
#define GC_NMAX 100000
#define GC_EMAX 3200000

// Scratch buffers (device globals — no allocation allowed)
__device__ float g_support[(size_t)GC_NMAX * GC_OUT];     // tanh(x@W)
__device__ int   g_counts [GC_NMAX];
__device__ int   g_offsets[GC_NMAX + 1];
__device__ int   g_cursor [GC_NMAX];
__device__ int   g_perm   [GC_EMAX];
__device__ int   g_partials[128];

// ---------------------------------------------------------------------------
// Kernel 1: SGEMM (M=N_nodes, K=512, N=256) with optional tanh epilogue.
// 128x128x16 tile, 8x8 register blocking, 256 threads. (unchanged from R1)
// ---------------------------------------------------------------------------
#define BM 128
#define BN 128
#define BK 16
#define TM 8
#define TN 8

__global__ __launch_bounds__(256, 2)
void gemm_tanh_kernel(const float* __restrict__ A,   // [M, 512]
                      const float* __restrict__ B,   // [512, 256]
                      const int*   __restrict__ active,
                      int M)
{
    const int K = GC_IN;
    const int N = GC_OUT;

    __shared__ float As[BK][BM];
    __shared__ float Bs[BK][BN];

    const int bcol = blockIdx.x;
    const int brow = blockIdx.y;
    const int tid  = threadIdx.x;

    const int tcol = tid % (BN / TN);
    const int trow = tid / (BN / TN);

    const int aInnerRow = tid / (BK / 4);
    const int aInnerCol = (tid % (BK / 4)) * 4;

    const int bInnerRow = tid / (BN / 4);
    const int bInnerCol = (tid % (BN / 4)) * 4;

    float acc[TM][TN];
    #pragma unroll
    for (int m = 0; m < TM; m++)
        #pragma unroll
        for (int n = 0; n < TN; n++)
            acc[m][n] = 0.0f;

    const int rowBase = brow * BM;

    for (int kb = 0; kb < K; kb += BK) {
        #pragma unroll
        for (int i = 0; i < BM; i += 64) {
            int r = rowBase + aInnerRow + i;
            float4 v;
            if (r < M) {
                v = *(const float4*)(A + (size_t)r * K + kb + aInnerCol);
            } else {
                v = make_float4(0.f, 0.f, 0.f, 0.f);
            }
            As[aInnerCol + 0][aInnerRow + i] = v.x;
            As[aInnerCol + 1][aInnerRow + i] = v.y;
            As[aInnerCol + 2][aInnerRow + i] = v.z;
            As[aInnerCol + 3][aInnerRow + i] = v.w;
        }
        #pragma unroll
        for (int i = 0; i < BK; i += 8) {
            int r = kb + bInnerRow + i;
            float4 v = *(const float4*)(B + (size_t)r * N + bcol * BN + bInnerCol);
            *(float4*)(&Bs[bInnerRow + i][bInnerCol]) = v;
        }
        __syncthreads();

        #pragma unroll
        for (int k = 0; k < BK; k++) {
            float regM[TM], regN[TN];
            #pragma unroll
            for (int m = 0; m < TM; m++) regM[m] = As[k][trow * TM + m];
            #pragma unroll
            for (int n = 0; n < TN; n++) regN[n] = Bs[k][tcol * TN + n];
            #pragma unroll
            for (int m = 0; m < TM; m++)
                #pragma unroll
                for (int n = 0; n < TN; n++)
                    acc[m][n] = fmaf(regM[m], regN[n], acc[m][n]);
        }
        __syncthreads();
    }

    const int act = active[0];

    #pragma unroll
    for (int m = 0; m < TM; m++) {
        int r = rowBase + trow * TM + m;
        if (r >= M) continue;
        #pragma unroll
        for (int n = 0; n < TN; n += 4) {
            int c = bcol * BN + tcol * TN + n;
            float4 v;
            v.x = acc[m][n + 0];
            v.y = acc[m][n + 1];
            v.z = acc[m][n + 2];
            v.w = acc[m][n + 3];
            if (act) {
                v.x = tanhf(v.x); v.y = tanhf(v.y);
                v.z = tanhf(v.z); v.w = tanhf(v.w);
            }
            *(float4*)(&g_support[(size_t)r * GC_OUT + c]) = v;
        }
    }
}

// ---------------------------------------------------------------------------
// CSR binning: zero counts -> histogram -> 3-kernel exclusive scan -> bin
// ---------------------------------------------------------------------------
__global__ void zero_counts_kernel(int N)
{
    int i = blockIdx.x * blockDim.x + threadIdx.x;
    if (i < N) g_counts[i] = 0;
}

__global__ void hist_kernel(const int* __restrict__ rows, int E)
{
    int i = blockIdx.x * blockDim.x + threadIdx.x;
    if (i < E) atomicAdd(&g_counts[rows[i]], 1);
}

#define SCAN_B 1024

// chunk-local exclusive scan, chunk totals to g_partials
__global__ __launch_bounds__(SCAN_B)
void scan1_kernel(int N)
{
    __shared__ int s[SCAN_B];
    int chunk = blockIdx.x;
    int i = chunk * SCAN_B + threadIdx.x;
    int v = (i < N) ? g_counts[i] : 0;
    s[threadIdx.x] = v;
    __syncthreads();
    for (int d = 1; d < SCAN_B; d <<= 1) {
        int t = (threadIdx.x >= d) ? s[threadIdx.x - d] : 0;
        __syncthreads();
        s[threadIdx.x] += t;
        __syncthreads();
    }
    if (i < N) g_offsets[i] = s[threadIdx.x] - v;     // exclusive, chunk-local
    if (threadIdx.x == SCAN_B - 1) g_partials[chunk] = s[SCAN_B - 1];
}

// exclusive scan of chunk totals (nchunks <= 128)
__global__ __launch_bounds__(128)
void scan2_kernel(int nchunks)
{
    __shared__ int s[128];
    int v = (threadIdx.x < nchunks) ? g_partials[threadIdx.x] : 0;
    s[threadIdx.x] = v;
    __syncthreads();
    for (int d = 1; d < 128; d <<= 1) {
        int t = (threadIdx.x >= d) ? s[threadIdx.x - d] : 0;
        __syncthreads();
        s[threadIdx.x] += t;
        __syncthreads();
    }
    if (threadIdx.x < nchunks) g_partials[threadIdx.x] = s[threadIdx.x] - v;
}

// add chunk base; init cursor; set offsets[N] = E
__global__ __launch_bounds__(SCAN_B)
void scan3_kernel(int N, int E)
{
    int i = blockIdx.x * SCAN_B + threadIdx.x;
    if (i < N) {
        int o = g_offsets[i] + g_partials[blockIdx.x];
        g_offsets[i] = o;
        g_cursor[i]  = o;
    }
    if (i == 0) g_offsets[N] = E;
}

__global__ void bin_kernel(const int* __restrict__ rows, int E)
{
    int i = blockIdx.x * blockDim.x + threadIdx.x;
    if (i < E) {
        int pos = atomicAdd(&g_cursor[rows[i]], 1);
        g_perm[pos] = i;
    }
}

// ---------------------------------------------------------------------------
// Kernel 3: CSR SpMM, one warp per output row, no atomics.
// acc[8] fp32 per lane (lane covers float4 #lane and #lane+32 of the row).
// ---------------------------------------------------------------------------
__global__ __launch_bounds__(256)
void spmm_csr_kernel(const int*   __restrict__ cols,
                     const float* __restrict__ vals,
                     float*       __restrict__ out,
                     int N)
{
    int warp = (blockIdx.x * blockDim.x + threadIdx.x) >> 5;
    int lane = threadIdx.x & 31;
    if (warp >= N) return;

    int beg = g_offsets[warp];
    int end = g_offsets[warp + 1];

    float4 a0 = make_float4(0.f, 0.f, 0.f, 0.f);
    float4 a1 = make_float4(0.f, 0.f, 0.f, 0.f);

    const float4* base = (const float4*)g_support;

    int idx = beg;
    for (; idx + 1 < end; idx += 2) {
        int e0 = g_perm[idx];
        int e1 = g_perm[idx + 1];
        int   c0 = __ldg(cols + e0);
        int   c1 = __ldg(cols + e1);
        float v0 = __ldg(vals + e0);
        float v1 = __ldg(vals + e1);
        const float4* s0 = base + (size_t)c0 * (GC_OUT / 4);
        const float4* s1 = base + (size_t)c1 * (GC_OUT / 4);
        float4 p00 = __ldg(s0 + lane);
        float4 p01 = __ldg(s0 + 32 + lane);
        float4 p10 = __ldg(s1 + lane);
        float4 p11 = __ldg(s1 + 32 + lane);
        a0.x = fmaf(v0, p00.x, a0.x); a0.y = fmaf(v0, p00.y, a0.y);
        a0.z = fmaf(v0, p00.z, a0.z); a0.w = fmaf(v0, p00.w, a0.w);
        a1.x = fmaf(v0, p01.x, a1.x); a1.y = fmaf(v0, p01.y, a1.y);
        a1.z = fmaf(v0, p01.z, a1.z); a1.w = fmaf(v0, p01.w, a1.w);
        a0.x = fmaf(v1, p10.x, a0.x); a0.y = fmaf(v1, p10.y, a0.y);
        a0.z = fmaf(v1, p10.z, a0.z); a0.w = fmaf(v1, p10.w, a0.w);
        a1.x = fmaf(v1, p11.x, a1.x); a1.y = fmaf(v1, p11.y, a1.y);
        a1.z = fmaf(v1, p11.z, a1.z); a1.w = fmaf(v1, p11.w, a1.w);
    }
    if (idx < end) {
        int e0 = g_perm[idx];
        int   c0 = __ldg(cols + e0);
        float v0 = __ldg(vals + e0);
        const float4* s0 = base + (size_t)c0 * (GC_OUT / 4);
        float4 p00 = __ldg(s0 + lane);
        float4 p01 = __ldg(s0 + 32 + lane);
        a0.x = fmaf(v0, p00.x, a0.x); a0.y = fmaf(v0, p00.y, a0.y);
        a0.z = fmaf(v0, p00.z, a0.z); a0.w = fmaf(v0, p00.w, a0.w);
        a1.x = fmaf(v0, p01.x, a1.x); a1.y = fmaf(v0, p01.y, a1.y);
        a1.z = fmaf(v0, p01.z, a1.z); a1.w = fmaf(v0, p01.w, a1.w);
    }

    float4* o = (float4*)(out + (size_t)warp * GC_OUT);
    o[lane]      = a0;
    o[lane + 32] = a1;
}

// ---------------------------------------------------------------------------
// Launch
// ---------------------------------------------------------------------------
extern "C" void kernel_launch(void* const* d_in, const int* in_sizes, int n_in,
                              void* d_out, int out_size)
{
    const float* x      = (const float*)d_in[0];
    const float* weight = (const float*)d_in[1];
    const int*   erows  = (const int*)d_in[2];
    const int*   ecols  = (const int*)d_in[3];
    const float* evals  = (const float*)d_in[4];
    const int*   active = (const int*)d_in[5];
    float* out = (float*)d_out;

    int N = in_sizes[0] / GC_IN;    // 100000
    int E = in_sizes[2];            // 3200000

    // 1) support = tanh(x @ W)
    dim3 ggrid(GC_OUT / BN, (N + BM - 1) / BM);
    gemm_tanh_kernel<<<ggrid, 256>>>(x, weight, active, N);

    // 2) CSR binning (runs concurrently-independent of GEMM except spmm)
    int nchunks = (N + SCAN_B - 1) / SCAN_B;          // 98
    zero_counts_kernel<<<(N + 255) / 256, 256>>>(N);
    hist_kernel<<<(E + 255) / 256, 256>>>(erows, E);
    scan1_kernel<<<nchunks, SCAN_B>>>(N);
    scan2_kernel<<<1, 128>>>(nchunks);
    scan3_kernel<<<nchunks, SCAN_B>>>(N, E);
    bin_kernel<<<(E + 255) / 256, 256>>>(erows, E);

    // 3) CSR SpMM: one warp per row, writes out exactly once (no zeroing, no atomics)
    long long threads = (long long)N * 32;
    int blocks = (int)((threads + 255) / 256);
    spmm_csr_kernel<<<blocks, 256>>>(ecols, evals, out, N);
}

// round 14
// speedup vs baseline: 1.0002x; 1.0000x over previous
#include <cuda_runtime.h>
#include <cuda_bf16.h>
#include <math.h>

// Problem constants (fixed shapes for this problem instance)
#define GC_IN   512
#define GC_OUT  256
#define GC_NMAX 100000
#define GC_EMAX 3200000

// Scratch buffers (device globals — no allocation allowed)
__device__ float g_support[(size_t)GC_NMAX * GC_OUT];     // tanh(x@W)
__device__ int   g_counts [GC_NMAX];
__device__ int   g_offsets[GC_NMAX + 1];
__device__ int   g_cursor [GC_NMAX];
__device__ int   g_perm   [GC_EMAX];
__device__ int   g_partials[128];

// ---------------------------------------------------------------------------
// Kernel 1: SGEMM (M=N_nodes, K=512, N=256) with optional tanh epilogue.
// 128x128x16 tile, 8x8 register blocking, 256 threads. (unchanged from R1)
// ---------------------------------------------------------------------------
#define BM 128
#define BN 128
#define BK 16
#define TM 8
#define TN 8

__global__ __launch_bounds__(256, 2)
void gemm_tanh_kernel(const float* __restrict__ A,   // [M, 512]
                      const float* __restrict__ B,   // [512, 256]
                      const int*   __restrict__ active,
                      int M)
{
    const int K = GC_IN;
    const int N = GC_OUT;

    __shared__ float As[BK][BM];
    __shared__ float Bs[BK][BN];

    const int bcol = blockIdx.x;
    const int brow = blockIdx.y;
    const int tid  = threadIdx.x;

    const int tcol = tid % (BN / TN);
    const int trow = tid / (BN / TN);

    const int aInnerRow = tid / (BK / 4);
    const int aInnerCol = (tid % (BK / 4)) * 4;

    const int bInnerRow = tid / (BN / 4);
    const int bInnerCol = (tid % (BN / 4)) * 4;

    float acc[TM][TN];
    #pragma unroll
    for (int m = 0; m < TM; m++)
        #pragma unroll
        for (int n = 0; n < TN; n++)
            acc[m][n] = 0.0f;

    const int rowBase = brow * BM;

    for (int kb = 0; kb < K; kb += BK) {
        #pragma unroll
        for (int i = 0; i < BM; i += 64) {
            int r = rowBase + aInnerRow + i;
            float4 v;
            if (r < M) {
                v = *(const float4*)(A + (size_t)r * K + kb + aInnerCol);
            } else {
                v = make_float4(0.f, 0.f, 0.f, 0.f);
            }
            As[aInnerCol + 0][aInnerRow + i] = v.x;
            As[aInnerCol + 1][aInnerRow + i] = v.y;
            As[aInnerCol + 2][aInnerRow + i] = v.z;
            As[aInnerCol + 3][aInnerRow + i] = v.w;
        }
        #pragma unroll
        for (int i = 0; i < BK; i += 8) {
            int r = kb + bInnerRow + i;
            float4 v = *(const float4*)(B + (size_t)r * N + bcol * BN + bInnerCol);
            *(float4*)(&Bs[bInnerRow + i][bInnerCol]) = v;
        }
        __syncthreads();

        #pragma unroll
        for (int k = 0; k < BK; k++) {
            float regM[TM], regN[TN];
            #pragma unroll
            for (int m = 0; m < TM; m++) regM[m] = As[k][trow * TM + m];
            #pragma unroll
            for (int n = 0; n < TN; n++) regN[n] = Bs[k][tcol * TN + n];
            #pragma unroll
            for (int m = 0; m < TM; m++)
                #pragma unroll
                for (int n = 0; n < TN; n++)
                    acc[m][n] = fmaf(regM[m], regN[n], acc[m][n]);
        }
        __syncthreads();
    }

    const int act = active[0];

    #pragma unroll
    for (int m = 0; m < TM; m++) {
        int r = rowBase + trow * TM + m;
        if (r >= M) continue;
        #pragma unroll
        for (int n = 0; n < TN; n += 4) {
            int c = bcol * BN + tcol * TN + n;
            float4 v;
            v.x = acc[m][n + 0];
            v.y = acc[m][n + 1];
            v.z = acc[m][n + 2];
            v.w = acc[m][n + 3];
            if (act) {
                v.x = tanhf(v.x); v.y = tanhf(v.y);
                v.z = tanhf(v.z); v.w = tanhf(v.w);
            }
            *(float4*)(&g_support[(size_t)r * GC_OUT + c]) = v;
        }
    }
}

// ---------------------------------------------------------------------------
// CSR binning: zero counts -> histogram -> 3-kernel exclusive scan -> bin
// ---------------------------------------------------------------------------
__global__ void zero_counts_kernel(int N)
{
    int i = blockIdx.x * blockDim.x + threadIdx.x;
    if (i < N) g_counts[i] = 0;
}

__global__ void hist_kernel(const int* __restrict__ rows, int E)
{
    int i = blockIdx.x * blockDim.x + threadIdx.x;
    if (i < E) atomicAdd(&g_counts[rows[i]], 1);
}

#define SCAN_B 1024

// chunk-local exclusive scan, chunk totals to g_partials
__global__ __launch_bounds__(SCAN_B)
void scan1_kernel(int N)
{
    __shared__ int s[SCAN_B];
    int chunk = blockIdx.x;
    int i = chunk * SCAN_B + threadIdx.x;
    int v = (i < N) ? g_counts[i] : 0;
    s[threadIdx.x] = v;
    __syncthreads();
    for (int d = 1; d < SCAN_B; d <<= 1) {
        int t = (threadIdx.x >= d) ? s[threadIdx.x - d] : 0;
        __syncthreads();
        s[threadIdx.x] += t;
        __syncthreads();
    }
    if (i < N) g_offsets[i] = s[threadIdx.x] - v;     // exclusive, chunk-local
    if (threadIdx.x == SCAN_B - 1) g_partials[chunk] = s[SCAN_B - 1];
}

// exclusive scan of chunk totals (nchunks <= 128)
__global__ __launch_bounds__(128)
void scan2_kernel(int nchunks)
{
    __shared__ int s[128];
    int v = (threadIdx.x < nchunks) ? g_partials[threadIdx.x] : 0;
    s[threadIdx.x] = v;
    __syncthreads();
    for (int d = 1; d < 128; d <<= 1) {
        int t = (threadIdx.x >= d) ? s[threadIdx.x - d] : 0;
        __syncthreads();
        s[threadIdx.x] += t;
        __syncthreads();
    }
    if (threadIdx.x < nchunks) g_partials[threadIdx.x] = s[threadIdx.x] - v;
}

// add chunk base; init cursor; set offsets[N] = E
__global__ __launch_bounds__(SCAN_B)
void scan3_kernel(int N, int E)
{
    int i = blockIdx.x * SCAN_B + threadIdx.x;
    if (i < N) {
        int o = g_offsets[i] + g_partials[blockIdx.x];
        g_offsets[i] = o;
        g_cursor[i]  = o;
    }
    if (i == 0) g_offsets[N] = E;
}

__global__ void bin_kernel(const int* __restrict__ rows, int E)
{
    int i = blockIdx.x * blockDim.x + threadIdx.x;
    if (i < E) {
        int pos = atomicAdd(&g_cursor[rows[i]], 1);
        g_perm[pos] = i;
    }
}

// ---------------------------------------------------------------------------
// Kernel 3: CSR SpMM, one warp per output row, no atomics.
// acc[8] fp32 per lane (lane covers float4 #lane and #lane+32 of the row).
// ---------------------------------------------------------------------------
__global__ __launch_bounds__(256)
void spmm_csr_kernel(const int*   __restrict__ cols,
                     const float* __restrict__ vals,
                     float*       __restrict__ out,
                     int N)
{
    int warp = (blockIdx.x * blockDim.x + threadIdx.x) >> 5;
    int lane = threadIdx.x & 31;
    if (warp >= N) return;

    int beg = g_offsets[warp];
    int end = g_offsets[warp + 1];

    float4 a0 = make_float4(0.f, 0.f, 0.f, 0.f);
    float4 a1 = make_float4(0.f, 0.f, 0.f, 0.f);

    const float4* base = (const float4*)g_support;

    int idx = beg;
    for (; idx + 1 < end; idx += 2) {
        int e0 = g_perm[idx];
        int e1 = g_perm[idx + 1];
        int   c0 = __ldg(cols + e0);
        int   c1 = __ldg(cols + e1);
        float v0 = __ldg(vals + e0);
        float v1 = __ldg(vals + e1);
        const float4* s0 = base + (size_t)c0 * (GC_OUT / 4);
        const float4* s1 = base + (size_t)c1 * (GC_OUT / 4);
        float4 p00 = __ldg(s0 + lane);
        float4 p01 = __ldg(s0 + 32 + lane);
        float4 p10 = __ldg(s1 + lane);
        float4 p11 = __ldg(s1 + 32 + lane);
        a0.x = fmaf(v0, p00.x, a0.x); a0.y = fmaf(v0, p00.y, a0.y);
        a0.z = fmaf(v0, p00.z, a0.z); a0.w = fmaf(v0, p00.w, a0.w);
        a1.x = fmaf(v0, p01.x, a1.x); a1.y = fmaf(v0, p01.y, a1.y);
        a1.z = fmaf(v0, p01.z, a1.z); a1.w = fmaf(v0, p01.w, a1.w);
        a0.x = fmaf(v1, p10.x, a0.x); a0.y = fmaf(v1, p10.y, a0.y);
        a0.z = fmaf(v1, p10.z, a0.z); a0.w = fmaf(v1, p10.w, a0.w);
        a1.x = fmaf(v1, p11.x, a1.x); a1.y = fmaf(v1, p11.y, a1.y);
        a1.z = fmaf(v1, p11.z, a1.z); a1.w = fmaf(v1, p11.w, a1.w);
    }
    if (idx < end) {
        int e0 = g_perm[idx];
        int   c0 = __ldg(cols + e0);
        float v0 = __ldg(vals + e0);
        const float4* s0 = base + (size_t)c0 * (GC_OUT / 4);
        float4 p00 = __ldg(s0 + lane);
        float4 p01 = __ldg(s0 + 32 + lane);
        a0.x = fmaf(v0, p00.x, a0.x); a0.y = fmaf(v0, p00.y, a0.y);
        a0.z = fmaf(v0, p00.z, a0.z); a0.w = fmaf(v0, p00.w, a0.w);
        a1.x = fmaf(v0, p01.x, a1.x); a1.y = fmaf(v0, p01.y, a1.y);
        a1.z = fmaf(v0, p01.z, a1.z); a1.w = fmaf(v0, p01.w, a1.w);
    }

    float4* o = (float4*)(out + (size_t)warp * GC_OUT);
    o[lane]      = a0;
    o[lane + 32] = a1;
}

// ---------------------------------------------------------------------------
// Launch
// ---------------------------------------------------------------------------
extern "C" void kernel_launch(void* const* d_in, const int* in_sizes, int n_in,
                              void* d_out, int out_size)
{
    const float* x      = (const float*)d_in[0];
    const float* weight = (const float*)d_in[1];
    const int*   erows  = (const int*)d_in[2];
    const int*   ecols  = (const int*)d_in[3];
    const float* evals  = (const float*)d_in[4];
    const int*   active = (const int*)d_in[5];
    float* out = (float*)d_out;

    int N = in_sizes[0] / GC_IN;    // 100000
    int E = in_sizes[2];            // 3200000

    // 1) support = tanh(x @ W)
    dim3 ggrid(GC_OUT / BN, (N + BM - 1) / BM);
    gemm_tanh_kernel<<<ggrid, 256>>>(x, weight, active, N);

    // 2) CSR binning (runs concurrently-independent of GEMM except spmm)
    int nchunks = (N + SCAN_B - 1) / SCAN_B;          // 98
    zero_counts_kernel<<<(N + 255) / 256, 256>>>(N);
    hist_kernel<<<(E + 255) / 256, 256>>>(erows, E);
    scan1_kernel<<<nchunks, SCAN_B>>>(N);
    scan2_kernel<<<1, 128>>>(nchunks);
    scan3_kernel<<<nchunks, SCAN_B>>>(N, E);
    bin_kernel<<<(E + 255) / 256, 256>>>(erows, E);

    // 3) CSR SpMM: one warp per row, writes out exactly once (no zeroing, no atomics)
    long long threads = (long long)N * 32;
    int blocks = (int)((threads + 255) / 256);
    spmm_csr_kernel<<<blocks, 256>>>(ecols, evals, out, N);
}

// round 15
// speedup vs baseline: 1.0008x; 1.0006x over previous
#include <cuda_runtime.h>
#include <cuda_bf16.h>
#include <math.h>

// Problem constants (fixed shapes for this problem instance)
#define GC_IN   512
#define GC_OUT  256
#define GC_NMAX 100000
#define GC_EMAX 3200000

// Scratch buffers (device globals — no allocation allowed)
__device__ float g_support[(size_t)GC_NMAX * GC_OUT];     // tanh(x@W)
__device__ int   g_counts [GC_NMAX];
__device__ int   g_offsets[GC_NMAX + 1];
__device__ int   g_cursor [GC_NMAX];
__device__ int   g_perm   [GC_EMAX];
__device__ int   g_partials[128];

// ---------------------------------------------------------------------------
// Kernel 1: SGEMM (M=N_nodes, K=512, N=256) with optional tanh epilogue.
// 128x128x16 tile, 8x8 register blocking, 256 threads. (unchanged from R1)
// ---------------------------------------------------------------------------
#define BM 128
#define BN 128
#define BK 16
#define TM 8
#define TN 8

__global__ __launch_bounds__(256, 2)
void gemm_tanh_kernel(const float* __restrict__ A,   // [M, 512]
                      const float* __restrict__ B,   // [512, 256]
                      const int*   __restrict__ active,
                      int M)
{
    const int K = GC_IN;
    const int N = GC_OUT;

    __shared__ float As[BK][BM];
    __shared__ float Bs[BK][BN];

    const int bcol = blockIdx.x;
    const int brow = blockIdx.y;
    const int tid  = threadIdx.x;

    const int tcol = tid % (BN / TN);
    const int trow = tid / (BN / TN);

    const int aInnerRow = tid / (BK / 4);
    const int aInnerCol = (tid % (BK / 4)) * 4;

    const int bInnerRow = tid / (BN / 4);
    const int bInnerCol = (tid % (BN / 4)) * 4;

    float acc[TM][TN];
    #pragma unroll
    for (int m = 0; m < TM; m++)
        #pragma unroll
        for (int n = 0; n < TN; n++)
            acc[m][n] = 0.0f;

    const int rowBase = brow * BM;

    for (int kb = 0; kb < K; kb += BK) {
        #pragma unroll
        for (int i = 0; i < BM; i += 64) {
            int r = rowBase + aInnerRow + i;
            float4 v;
            if (r < M) {
                v = *(const float4*)(A + (size_t)r * K + kb + aInnerCol);
            } else {
                v = make_float4(0.f, 0.f, 0.f, 0.f);
            }
            As[aInnerCol + 0][aInnerRow + i] = v.x;
            As[aInnerCol + 1][aInnerRow + i] = v.y;
            As[aInnerCol + 2][aInnerRow + i] = v.z;
            As[aInnerCol + 3][aInnerRow + i] = v.w;
        }
        #pragma unroll
        for (int i = 0; i < BK; i += 8) {
            int r = kb + bInnerRow + i;
            float4 v = *(const float4*)(B + (size_t)r * N + bcol * BN + bInnerCol);
            *(float4*)(&Bs[bInnerRow + i][bInnerCol]) = v;
        }
        __syncthreads();

        #pragma unroll
        for (int k = 0; k < BK; k++) {
            float regM[TM], regN[TN];
            #pragma unroll
            for (int m = 0; m < TM; m++) regM[m] = As[k][trow * TM + m];
            #pragma unroll
            for (int n = 0; n < TN; n++) regN[n] = Bs[k][tcol * TN + n];
            #pragma unroll
            for (int m = 0; m < TM; m++)
                #pragma unroll
                for (int n = 0; n < TN; n++)
                    acc[m][n] = fmaf(regM[m], regN[n], acc[m][n]);
        }
        __syncthreads();
    }

    const int act = active[0];

    #pragma unroll
    for (int m = 0; m < TM; m++) {
        int r = rowBase + trow * TM + m;
        if (r >= M) continue;
        #pragma unroll
        for (int n = 0; n < TN; n += 4) {
            int c = bcol * BN + tcol * TN + n;
            float4 v;
            v.x = acc[m][n + 0];
            v.y = acc[m][n + 1];
            v.z = acc[m][n + 2];
            v.w = acc[m][n + 3];
            if (act) {
                v.x = tanhf(v.x); v.y = tanhf(v.y);
                v.z = tanhf(v.z); v.w = tanhf(v.w);
            }
            *(float4*)(&g_support[(size_t)r * GC_OUT + c]) = v;
        }
    }
}

// ---------------------------------------------------------------------------
// CSR binning: zero counts -> histogram -> 3-kernel exclusive scan -> bin
// ---------------------------------------------------------------------------
__global__ void zero_counts_kernel(int N)
{
    int i = blockIdx.x * blockDim.x + threadIdx.x;
    if (i < N) g_counts[i] = 0;
}

__global__ void hist_kernel(const int* __restrict__ rows, int E)
{
    int i = blockIdx.x * blockDim.x + threadIdx.x;
    if (i < E) atomicAdd(&g_counts[rows[i]], 1);
}

#define SCAN_B 1024

// chunk-local exclusive scan, chunk totals to g_partials
__global__ __launch_bounds__(SCAN_B)
void scan1_kernel(int N)
{
    __shared__ int s[SCAN_B];
    int chunk = blockIdx.x;
    int i = chunk * SCAN_B + threadIdx.x;
    int v = (i < N) ? g_counts[i] : 0;
    s[threadIdx.x] = v;
    __syncthreads();
    for (int d = 1; d < SCAN_B; d <<= 1) {
        int t = (threadIdx.x >= d) ? s[threadIdx.x - d] : 0;
        __syncthreads();
        s[threadIdx.x] += t;
        __syncthreads();
    }
    if (i < N) g_offsets[i] = s[threadIdx.x] - v;     // exclusive, chunk-local
    if (threadIdx.x == SCAN_B - 1) g_partials[chunk] = s[SCAN_B - 1];
}

// exclusive scan of chunk totals (nchunks <= 128)
__global__ __launch_bounds__(128)
void scan2_kernel(int nchunks)
{
    __shared__ int s[128];
    int v = (threadIdx.x < nchunks) ? g_partials[threadIdx.x] : 0;
    s[threadIdx.x] = v;
    __syncthreads();
    for (int d = 1; d < 128; d <<= 1) {
        int t = (threadIdx.x >= d) ? s[threadIdx.x - d] : 0;
        __syncthreads();
        s[threadIdx.x] += t;
        __syncthreads();
    }
    if (threadIdx.x < nchunks) g_partials[threadIdx.x] = s[threadIdx.x] - v;
}

// add chunk base; init cursor; set offsets[N] = E
__global__ __launch_bounds__(SCAN_B)
void scan3_kernel(int N, int E)
{
    int i = blockIdx.x * SCAN_B + threadIdx.x;
    if (i < N) {
        int o = g_offsets[i] + g_partials[blockIdx.x];
        g_offsets[i] = o;
        g_cursor[i]  = o;
    }
    if (i == 0) g_offsets[N] = E;
}

__global__ void bin_kernel(const int* __restrict__ rows, int E)
{
    int i = blockIdx.x * blockDim.x + threadIdx.x;
    if (i < E) {
        int pos = atomicAdd(&g_cursor[rows[i]], 1);
        g_perm[pos] = i;
    }
}

// ---------------------------------------------------------------------------
// Kernel 3: CSR SpMM, one warp per output row, no atomics.
// acc[8] fp32 per lane (lane covers float4 #lane and #lane+32 of the row).
// ---------------------------------------------------------------------------
__global__ __launch_bounds__(256)
void spmm_csr_kernel(const int*   __restrict__ cols,
                     const float* __restrict__ vals,
                     float*       __restrict__ out,
                     int N)
{
    int warp = (blockIdx.x * blockDim.x + threadIdx.x) >> 5;
    int lane = threadIdx.x & 31;
    if (warp >= N) return;

    int beg = g_offsets[warp];
    int end = g_offsets[warp + 1];

    float4 a0 = make_float4(0.f, 0.f, 0.f, 0.f);
    float4 a1 = make_float4(0.f, 0.f, 0.f, 0.f);

    const float4* base = (const float4*)g_support;

    int idx = beg;
    for (; idx + 1 < end; idx += 2) {
        int e0 = g_perm[idx];
        int e1 = g_perm[idx + 1];
        int   c0 = __ldg(cols + e0);
        int   c1 = __ldg(cols + e1);
        float v0 = __ldg(vals + e0);
        float v1 = __ldg(vals + e1);
        const float4* s0 = base + (size_t)c0 * (GC_OUT / 4);
        const float4* s1 = base + (size_t)c1 * (GC_OUT / 4);
        float4 p00 = __ldg(s0 + lane);
        float4 p01 = __ldg(s0 + 32 + lane);
        float4 p10 = __ldg(s1 + lane);
        float4 p11 = __ldg(s1 + 32 + lane);
        a0.x = fmaf(v0, p00.x, a0.x); a0.y = fmaf(v0, p00.y, a0.y);
        a0.z = fmaf(v0, p00.z, a0.z); a0.w = fmaf(v0, p00.w, a0.w);
        a1.x = fmaf(v0, p01.x, a1.x); a1.y = fmaf(v0, p01.y, a1.y);
        a1.z = fmaf(v0, p01.z, a1.z); a1.w = fmaf(v0, p01.w, a1.w);
        a0.x = fmaf(v1, p10.x, a0.x); a0.y = fmaf(v1, p10.y, a0.y);
        a0.z = fmaf(v1, p10.z, a0.z); a0.w = fmaf(v1, p10.w, a0.w);
        a1.x = fmaf(v1, p11.x, a1.x); a1.y = fmaf(v1, p11.y, a1.y);
        a1.z = fmaf(v1, p11.z, a1.z); a1.w = fmaf(v1, p11.w, a1.w);
    }
    if (idx < end) {
        int e0 = g_perm[idx];
        int   c0 = __ldg(cols + e0);
        float v0 = __ldg(vals + e0);
        const float4* s0 = base + (size_t)c0 * (GC_OUT / 4);
        float4 p00 = __ldg(s0 + lane);
        float4 p01 = __ldg(s0 + 32 + lane);
        a0.x = fmaf(v0, p00.x, a0.x); a0.y = fmaf(v0, p00.y, a0.y);
        a0.z = fmaf(v0, p00.z, a0.z); a0.w = fmaf(v0, p00.w, a0.w);
        a1.x = fmaf(v0, p01.x, a1.x); a1.y = fmaf(v0, p01.y, a1.y);
        a1.z = fmaf(v0, p01.z, a1.z); a1.w = fmaf(v0, p01.w, a1.w);
    }

    float4* o = (float4*)(out + (size_t)warp * GC_OUT);
    o[lane]      = a0;
    o[lane + 32] = a1;
}

// ---------------------------------------------------------------------------
// Launch
// ---------------------------------------------------------------------------
extern "C" void kernel_launch(void* const* d_in, const int* in_sizes, int n_in,
                              void* d_out, int out_size)
{
    const float* x      = (const float*)d_in[0];
    const float* weight = (const float*)d_in[1];
    const int*   erows  = (const int*)d_in[2];
    const int*   ecols  = (const int*)d_in[3];
    const float* evals  = (const float*)d_in[4];
    const int*   active = (const int*)d_in[5];
    float* out = (float*)d_out;

    int N = in_sizes[0] / GC_IN;    // 100000
    int E = in_sizes[2];            // 3200000

    // 1) support = tanh(x @ W)
    dim3 ggrid(GC_OUT / BN, (N + BM - 1) / BM);
    gemm_tanh_kernel<<<ggrid, 256>>>(x, weight, active, N);

    // 2) CSR binning (runs concurrently-independent of GEMM except spmm)
    int nchunks = (N + SCAN_B - 1) / SCAN_B;          // 98
    zero_counts_kernel<<<(N + 255) / 256, 256>>>(N);
    hist_kernel<<<(E + 255) / 256, 256>>>(erows, E);
    scan1_kernel<<<nchunks, SCAN_B>>>(N);
    scan2_kernel<<<1, 128>>>(nchunks);
    scan3_kernel<<<nchunks, SCAN_B>>>(N, E);
    bin_kernel<<<(E + 255) / 256, 256>>>(erows, E);

    // 3) CSR SpMM: one warp per row, writes out exactly once (no zeroing, no atomics)
    long long threads = (long long)N * 32;
    int blocks = (int)((threads + 255) / 256);
    spmm_csr_kernel<<<blocks, 256>>>(ecols, evals, out, N);
}

// round 16
// speedup vs baseline: 1.0016x; 1.0009x over previous
#include <cuda_runtime.h>
#include <cuda_bf16.h>
#include <math.h>

// Problem constants (fixed shapes for this problem instance)
#define GC_IN   512
#define GC_OUT  256
#define GC_NMAX 100000
#define GC_EMAX 3200000

// Scratch buffers (device globals — no allocation allowed)
__device__ float g_support[(size_t)GC_NMAX * GC_OUT];     // tanh(x@W)
__device__ int   g_counts [GC_NMAX];
__device__ int   g_offsets[GC_NMAX + 1];
__device__ int   g_cursor [GC_NMAX];
__device__ int   g_perm   [GC_EMAX];
__device__ int   g_partials[128];

// ---------------------------------------------------------------------------
// Kernel 1: SGEMM (M=N_nodes, K=512, N=256) with optional tanh epilogue.
// 128x128x16 tile, 8x8 register blocking, 256 threads. (unchanged from R1)
// ---------------------------------------------------------------------------
#define BM 128
#define BN 128
#define BK 16
#define TM 8
#define TN 8

__global__ __launch_bounds__(256, 2)
void gemm_tanh_kernel(const float* __restrict__ A,   // [M, 512]
                      const float* __restrict__ B,   // [512, 256]
                      const int*   __restrict__ active,
                      int M)
{
    const int K = GC_IN;
    const int N = GC_OUT;

    __shared__ float As[BK][BM];
    __shared__ float Bs[BK][BN];

    const int bcol = blockIdx.x;
    const int brow = blockIdx.y;
    const int tid  = threadIdx.x;

    const int tcol = tid % (BN / TN);
    const int trow = tid / (BN / TN);

    const int aInnerRow = tid / (BK / 4);
    const int aInnerCol = (tid % (BK / 4)) * 4;

    const int bInnerRow = tid / (BN / 4);
    const int bInnerCol = (tid % (BN / 4)) * 4;

    float acc[TM][TN];
    #pragma unroll
    for (int m = 0; m < TM; m++)
        #pragma unroll
        for (int n = 0; n < TN; n++)
            acc[m][n] = 0.0f;

    const int rowBase = brow * BM;

    for (int kb = 0; kb < K; kb += BK) {
        #pragma unroll
        for (int i = 0; i < BM; i += 64) {
            int r = rowBase + aInnerRow + i;
            float4 v;
            if (r < M) {
                v = *(const float4*)(A + (size_t)r * K + kb + aInnerCol);
            } else {
                v = make_float4(0.f, 0.f, 0.f, 0.f);
            }
            As[aInnerCol + 0][aInnerRow + i] = v.x;
            As[aInnerCol + 1][aInnerRow + i] = v.y;
            As[aInnerCol + 2][aInnerRow + i] = v.z;
            As[aInnerCol + 3][aInnerRow + i] = v.w;
        }
        #pragma unroll
        for (int i = 0; i < BK; i += 8) {
            int r = kb + bInnerRow + i;
            float4 v = *(const float4*)(B + (size_t)r * N + bcol * BN + bInnerCol);
            *(float4*)(&Bs[bInnerRow + i][bInnerCol]) = v;
        }
        __syncthreads();

        #pragma unroll
        for (int k = 0; k < BK; k++) {
            float regM[TM], regN[TN];
            #pragma unroll
            for (int m = 0; m < TM; m++) regM[m] = As[k][trow * TM + m];
            #pragma unroll
            for (int n = 0; n < TN; n++) regN[n] = Bs[k][tcol * TN + n];
            #pragma unroll
            for (int m = 0; m < TM; m++)
                #pragma unroll
                for (int n = 0; n < TN; n++)
                    acc[m][n] = fmaf(regM[m], regN[n], acc[m][n]);
        }
        __syncthreads();
    }

    const int act = active[0];

    #pragma unroll
    for (int m = 0; m < TM; m++) {
        int r = rowBase + trow * TM + m;
        if (r >= M) continue;
        #pragma unroll
        for (int n = 0; n < TN; n += 4) {
            int c = bcol * BN + tcol * TN + n;
            float4 v;
            v.x = acc[m][n + 0];
            v.y = acc[m][n + 1];
            v.z = acc[m][n + 2];
            v.w = acc[m][n + 3];
            if (act) {
                v.x = tanhf(v.x); v.y = tanhf(v.y);
                v.z = tanhf(v.z); v.w = tanhf(v.w);
            }
            *(float4*)(&g_support[(size_t)r * GC_OUT + c]) = v;
        }
    }
}

// ---------------------------------------------------------------------------
// CSR binning: zero counts -> histogram -> 3-kernel exclusive scan -> bin
// ---------------------------------------------------------------------------
__global__ void zero_counts_kernel(int N)
{
    int i = blockIdx.x * blockDim.x + threadIdx.x;
    if (i < N) g_counts[i] = 0;
}

__global__ void hist_kernel(const int* __restrict__ rows, int E)
{
    int i = blockIdx.x * blockDim.x + threadIdx.x;
    if (i < E) atomicAdd(&g_counts[rows[i]], 1);
}

#define SCAN_B 1024

// chunk-local exclusive scan, chunk totals to g_partials
__global__ __launch_bounds__(SCAN_B)
void scan1_kernel(int N)
{
    __shared__ int s[SCAN_B];
    int chunk = blockIdx.x;
    int i = chunk * SCAN_B + threadIdx.x;
    int v = (i < N) ? g_counts[i] : 0;
    s[threadIdx.x] = v;
    __syncthreads();
    for (int d = 1; d < SCAN_B; d <<= 1) {
        int t = (threadIdx.x >= d) ? s[threadIdx.x - d] : 0;
        __syncthreads();
        s[threadIdx.x] += t;
        __syncthreads();
    }
    if (i < N) g_offsets[i] = s[threadIdx.x] - v;     // exclusive, chunk-local
    if (threadIdx.x == SCAN_B - 1) g_partials[chunk] = s[SCAN_B - 1];
}

// exclusive scan of chunk totals (nchunks <= 128)
__global__ __launch_bounds__(128)
void scan2_kernel(int nchunks)
{
    __shared__ int s[128];
    int v = (threadIdx.x < nchunks) ? g_partials[threadIdx.x] : 0;
    s[threadIdx.x] = v;
    __syncthreads();
    for (int d = 1; d < 128; d <<= 1) {
        int t = (threadIdx.x >= d) ? s[threadIdx.x - d] : 0;
        __syncthreads();
        s[threadIdx.x] += t;
        __syncthreads();
    }
    if (threadIdx.x < nchunks) g_partials[threadIdx.x] = s[threadIdx.x] - v;
}

// add chunk base; init cursor; set offsets[N] = E
__global__ __launch_bounds__(SCAN_B)
void scan3_kernel(int N, int E)
{
    int i = blockIdx.x * SCAN_B + threadIdx.x;
    if (i < N) {
        int o = g_offsets[i] + g_partials[blockIdx.x];
        g_offsets[i] = o;
        g_cursor[i]  = o;
    }
    if (i == 0) g_offsets[N] = E;
}

__global__ void bin_kernel(const int* __restrict__ rows, int E)
{
    int i = blockIdx.x * blockDim.x + threadIdx.x;
    if (i < E) {
        int pos = atomicAdd(&g_cursor[rows[i]], 1);
        g_perm[pos] = i;
    }
}

// ---------------------------------------------------------------------------
// Kernel 3: CSR SpMM, one warp per output row, no atomics.
// acc[8] fp32 per lane (lane covers float4 #lane and #lane+32 of the row).
// ---------------------------------------------------------------------------
__global__ __launch_bounds__(256)
void spmm_csr_kernel(const int*   __restrict__ cols,
                     const float* __restrict__ vals,
                     float*       __restrict__ out,
                     int N)
{
    int warp = (blockIdx.x * blockDim.x + threadIdx.x) >> 5;
    int lane = threadIdx.x & 31;
    if (warp >= N) return;

    int beg = g_offsets[warp];
    int end = g_offsets[warp + 1];

    float4 a0 = make_float4(0.f, 0.f, 0.f, 0.f);
    float4 a1 = make_float4(0.f, 0.f, 0.f, 0.f);

    const float4* base = (const float4*)g_support;

    int idx = beg;
    for (; idx + 1 < end; idx += 2) {
        int e0 = g_perm[idx];
        int e1 = g_perm[idx + 1];
        int   c0 = __ldg(cols + e0);
        int   c1 = __ldg(cols + e1);
        float v0 = __ldg(vals + e0);
        float v1 = __ldg(vals + e1);
        const float4* s0 = base + (size_t)c0 * (GC_OUT / 4);
        const float4* s1 = base + (size_t)c1 * (GC_OUT / 4);
        float4 p00 = __ldg(s0 + lane);
        float4 p01 = __ldg(s0 + 32 + lane);
        float4 p10 = __ldg(s1 + lane);
        float4 p11 = __ldg(s1 + 32 + lane);
        a0.x = fmaf(v0, p00.x, a0.x); a0.y = fmaf(v0, p00.y, a0.y);
        a0.z = fmaf(v0, p00.z, a0.z); a0.w = fmaf(v0, p00.w, a0.w);
        a1.x = fmaf(v0, p01.x, a1.x); a1.y = fmaf(v0, p01.y, a1.y);
        a1.z = fmaf(v0, p01.z, a1.z); a1.w = fmaf(v0, p01.w, a1.w);
        a0.x = fmaf(v1, p10.x, a0.x); a0.y = fmaf(v1, p10.y, a0.y);
        a0.z = fmaf(v1, p10.z, a0.z); a0.w = fmaf(v1, p10.w, a0.w);
        a1.x = fmaf(v1, p11.x, a1.x); a1.y = fmaf(v1, p11.y, a1.y);
        a1.z = fmaf(v1, p11.z, a1.z); a1.w = fmaf(v1, p11.w, a1.w);
    }
    if (idx < end) {
        int e0 = g_perm[idx];
        int   c0 = __ldg(cols + e0);
        float v0 = __ldg(vals + e0);
        const float4* s0 = base + (size_t)c0 * (GC_OUT / 4);
        float4 p00 = __ldg(s0 + lane);
        float4 p01 = __ldg(s0 + 32 + lane);
        a0.x = fmaf(v0, p00.x, a0.x); a0.y = fmaf(v0, p00.y, a0.y);
        a0.z = fmaf(v0, p00.z, a0.z); a0.w = fmaf(v0, p00.w, a0.w);
        a1.x = fmaf(v0, p01.x, a1.x); a1.y = fmaf(v0, p01.y, a1.y);
        a1.z = fmaf(v0, p01.z, a1.z); a1.w = fmaf(v0, p01.w, a1.w);
    }

    float4* o = (float4*)(out + (size_t)warp * GC_OUT);
    o[lane]      = a0;
    o[lane + 32] = a1;
}

// ---------------------------------------------------------------------------
// Launch
// ---------------------------------------------------------------------------
extern "C" void kernel_launch(void* const* d_in, const int* in_sizes, int n_in,
                              void* d_out, int out_size)
{
    const float* x      = (const float*)d_in[0];
    const float* weight = (const float*)d_in[1];
    const int*   erows  = (const int*)d_in[2];
    const int*   ecols  = (const int*)d_in[3];
    const float* evals  = (const float*)d_in[4];
    const int*   active = (const int*)d_in[5];
    float* out = (float*)d_out;

    int N = in_sizes[0] / GC_IN;    // 100000
    int E = in_sizes[2];            // 3200000

    // 1) support = tanh(x @ W)
    dim3 ggrid(GC_OUT / BN, (N + BM - 1) / BM);
    gemm_tanh_kernel<<<ggrid, 256>>>(x, weight, active, N);

    // 2) CSR binning (runs concurrently-independent of GEMM except spmm)
    int nchunks = (N + SCAN_B - 1) / SCAN_B;          // 98
    zero_counts_kernel<<<(N + 255) / 256, 256>>>(N);
    hist_kernel<<<(E + 255) / 256, 256>>>(erows, E);
    scan1_kernel<<<nchunks, SCAN_B>>>(N);
    scan2_kernel<<<1, 128>>>(nchunks);
    scan3_kernel<<<nchunks, SCAN_B>>>(N, E);
    bin_kernel<<<(E + 255) / 256, 256>>>(erows, E);

    // 3) CSR SpMM: one warp per row, writes out exactly once (no zeroing, no atomics)
    long long threads = (long long)N * 32;
    int blocks = (int)((threads + 255) / 256);
    spmm_csr_kernel<<<blocks, 256>>>(ecols, evals, out, N);
}